// round 10
// baseline (speedup 1.0000x reference)
#include <cuda_runtime.h>
#include <cuda_bf16.h>
#include <math.h>
#include <stdint.h>

#define NB   16
#define SQ   256
#define MM   768
#define TK   10
#define ROWS (NB*SQ)        // 4096
#define HID  (4*MM)         // 3072
#define EPS  1e-5f

// ---------------- static scratch (allocation-free rule) ----------------
__device__ float g_s [ROWS*MM];
__device__ float g_v [ROWS*MM];
__device__ float g_pe[SQ*MM];

__device__ __nv_bfloat16 g_xh [ROWS*MM],  g_xl [ROWS*MM];
__device__ __nv_bfloat16 g_snh[ROWS*MM],  g_snl[ROWS*MM];
__device__ __nv_bfloat16 g_imh[ROWS*MM],  g_iml[ROWS*MM];
__device__ __nv_bfloat16 g_hh [ROWS*HID], g_hl [ROWS*HID];

__device__ __nv_bfloat16 g_wh [MM*MM],      g_wl [MM*MM];
__device__ __nv_bfloat16 g_wvh[TK*MM*MM],   g_wvl[TK*MM*MM];
__device__ __nv_bfloat16 g_woh[TK*MM*MM],   g_wol[TK*MM*MM];
__device__ __nv_bfloat16 g_f1h[HID*MM],     g_f1l[HID*MM];
__device__ __nv_bfloat16 g_f2h[MM*HID],     g_f2l[MM*HID];

// ---------------- small helpers ----------------------------------------
__device__ __forceinline__ uint32_t s2u(const void* p) {
    uint32_t a;
    asm("{ .reg .u64 t; cvta.to.shared.u64 t, %1; cvt.u32.u64 %0, t; }"
        : "=r"(a) : "l"(p));
    return a;
}
__device__ __forceinline__ void cp16(uint32_t sdst, const void* gsrc) {
    asm volatile("cp.async.cg.shared.global [%0], [%1], 16;"
                 :: "r"(sdst), "l"(gsrc) : "memory");
}
__device__ __forceinline__ void cp_commit() {
    asm volatile("cp.async.commit_group;" ::: "memory");
}
template <int N>
__device__ __forceinline__ void cp_wait() {
    asm volatile("cp.async.wait_group %0;" :: "n"(N) : "memory");
}
__device__ __forceinline__ void ldmx4(uint32_t& r0, uint32_t& r1,
                                      uint32_t& r2, uint32_t& r3, uint32_t a) {
    asm volatile("ldmatrix.sync.aligned.m8n8.x4.shared.b16 {%0,%1,%2,%3}, [%4];"
                 : "=r"(r0), "=r"(r1), "=r"(r2), "=r"(r3) : "r"(a));
}
__device__ __forceinline__ void mma16816(float* d, const uint32_t* a,
                                         uint32_t b0, uint32_t b1) {
    asm volatile("mma.sync.aligned.m16n8k16.row.col.f32.bf16.bf16.f32 "
                 "{%0,%1,%2,%3}, {%4,%5,%6,%7}, {%8,%9}, {%0,%1,%2,%3};"
                 : "+f"(d[0]), "+f"(d[1]), "+f"(d[2]), "+f"(d[3])
                 : "r"(a[0]), "r"(a[1]), "r"(a[2]), "r"(a[3]),
                   "r"(b0), "r"(b1));
}
__device__ __forceinline__ void split1(float x, __nv_bfloat16* h, __nv_bfloat16* l) {
    __nv_bfloat16 hi = __float2bfloat16(x);
    *h = hi;
    *l = __float2bfloat16(x - __bfloat162float(hi));
}

// ---------------- prep kernels (fused: fewer launches, aligns ncu) ------
// prep_a: split x + weight, compute PE (fp64, matches reference)
__global__ __launch_bounds__(256) void prep_a(
    const float* __restrict__ x, __nv_bfloat16* __restrict__ xh, __nv_bfloat16* __restrict__ xl,
    const float* __restrict__ w, __nv_bfloat16* __restrict__ wh, __nv_bfloat16* __restrict__ wl,
    float* __restrict__ pe)
{
    int stride = gridDim.x * blockDim.x;
    int t = blockIdx.x * blockDim.x + threadIdx.x;
    for (int i = t; i < ROWS * MM; i += stride) split1(x[i], xh + i, xl + i);
    for (int i = t; i < MM * MM; i += stride)   split1(w[i], wh + i, wl + i);
    for (int i = t; i < SQ * MM; i += stride) {
        int j = i / MM, m = i % MM, z = m & ~1;
        double ang = (double)j * exp(-((double)(2 * z) / (double)MM) * log(10000.0));
        pe[i] = (float)((m & 1) ? cos(ang) : sin(ang));
    }
}
// prep_pair: split two equal-size fp32 tensors
__global__ __launch_bounds__(256) void prep_pair(
    const float* __restrict__ a, __nv_bfloat16* __restrict__ ah, __nv_bfloat16* __restrict__ al,
    const float* __restrict__ b, __nv_bfloat16* __restrict__ bh, __nv_bfloat16* __restrict__ bl,
    int n)
{
    int stride = gridDim.x * blockDim.x;
    int t = blockIdx.x * blockDim.x + threadIdx.x;
    for (int i = t; i < n; i += stride) {
        split1(a[i], ah + i, al + i);
        split1(b[i], bh + i, bl + i);
    }
}

// ---------------- LayerNorm (+optional residual) -> hi/lo bf16 ---------
template <bool ADDRES>
__global__ __launch_bounds__(256) void ln_split_kernel(
    const float* __restrict__ in, const float* __restrict__ g,
    const float* __restrict__ b, __nv_bfloat16* __restrict__ oh,
    __nv_bfloat16* __restrict__ ol)
{
    int r = blockIdx.x;
    int tid = threadIdx.x;
    const float* row = in + (size_t)r * MM;
    float x0 = row[tid], x1 = row[tid + 256], x2 = row[tid + 512];

    __shared__ float sd[256];
    sd[tid] = x0 + x1 + x2;
    __syncthreads();
    #pragma unroll
    for (int o = 128; o > 0; o >>= 1) { if (tid < o) sd[tid] += sd[tid + o]; __syncthreads(); }
    float mu = sd[0] * (1.0f / (float)MM);
    __syncthreads();

    float d0 = x0 - mu, d1 = x1 - mu, d2 = x2 - mu;
    sd[tid] = d0 * d0 + d1 * d1 + d2 * d2;
    __syncthreads();
    #pragma unroll
    for (int o = 128; o > 0; o >>= 1) { if (tid < o) sd[tid] += sd[tid + o]; __syncthreads(); }
    float rstd = rsqrtf(sd[0] * (1.0f / (float)MM) + EPS);

    size_t base = (size_t)r * MM;
    float v0 = d0 * rstd * g[tid]       + b[tid]       + (ADDRES ? x0 : 0.f);
    float v1 = d1 * rstd * g[tid + 256] + b[tid + 256] + (ADDRES ? x1 : 0.f);
    float v2 = d2 * rstd * g[tid + 512] + b[tid + 512] + (ADDRES ? x2 : 0.f);
    split1(v0, oh + base + tid,       ol + base + tid);
    split1(v1, oh + base + tid + 256, ol + base + tid + 256);
    split1(v2, oh + base + tid + 512, ol + base + tid + 512);
}

// ---------------- exclusive token prefix sum -> hi/lo bf16 -------------
__global__ __launch_bounds__(256) void scan_split_kernel(
    const float* __restrict__ v, __nv_bfloat16* __restrict__ oh,
    __nv_bfloat16* __restrict__ ol)
{
    int idx = blockIdx.x * 256 + threadIdx.x;     // 0..12287 = (n,d)
    int n = idx / MM;
    int d = idx % MM;
    const float* src = v + (size_t)n * SQ * MM + d;
    size_t base = (size_t)n * SQ * MM + d;
    float acc = 0.f;
    #pragma unroll 8
    for (int j = 0; j < SQ; j++) {
        __nv_bfloat16 h = __float2bfloat16(acc);
        oh[base + (size_t)j * MM] = h;
        ol[base + (size_t)j * MM] = __float2bfloat16(acc - __bfloat162float(h));
        acc += src[(size_t)j * MM];
    }
}

// ---------------- HMMA GEMM: C = A @ W^T, bf16x3 split ------------------
// Tile 128x128, BK=64, 8 warps (64x32 each), 2-stage cp.async pipeline,
// ONE __syncthreads per iteration. SMEM pitch 144B (conflict-free phases).
// EPI: 0 = fp32; 1 = fp32+PE; 2 = fp32+residual; 3 = bias+GELU->hi/lo; 4 = fp32+bias.
#define PITCH  144
#define ATILE  (128 * PITCH)          // 18432
#define GBUF   (2 * ATILE)            // A + B per stage = 36864
#define SMEMB  (2 * GBUF)             // 73728

template <int EPI>
__global__ __launch_bounds__(256, 2) void hmma_gemm(
    const __nv_bfloat16* __restrict__ Ah, const __nv_bfloat16* __restrict__ Al,
    const __nv_bfloat16* __restrict__ Wh, const __nv_bfloat16* __restrict__ Wl,
    const float* __restrict__ bias, const float* __restrict__ extra,
    float* __restrict__ Cf, __nv_bfloat16* __restrict__ Chi,
    __nv_bfloat16* __restrict__ Clo, int Nc, int K)
{
    extern __shared__ __align__(16) char smem[];
    const uint32_t sb = s2u(smem);
    const int tid = threadIdx.x, wid = tid >> 5, lane = tid & 31;
    const int tm = blockIdx.y * 128, tn = blockIdx.x * 128;
    const int wm = (wid & 1) * 64;       // warp row offset
    const int wn = (wid >> 1) * 32;      // warp col offset

    const int KC = K / 64;               // chunks per pass
    const int NC = 3 * KC;               // total chunks (3 split passes)

    float acc[4][4][4];
    #pragma unroll
    for (int i = 0; i < 4; i++)
        #pragma unroll
        for (int j = 0; j < 4; j++)
            #pragma unroll
            for (int t = 0; t < 4; t++) acc[i][j][t] = 0.f;

    const int lrow = tid >> 1;                   // not used directly; see issue
    (void)lrow;

    auto issue = [&](int c) {
        int pass = c / KC;
        int kk = (c - pass * KC) * 64;
        const __nv_bfloat16* Ap = (pass == 2) ? Al : Ah;
        const __nv_bfloat16* Bp = (pass == 1) ? Wl : Wh;
        uint32_t s0 = sb + (c & 1) * GBUF;
        // A: 128 rows x 128B = 1024 cp16; 4 per thread
        #pragma unroll
        for (int i = 0; i < 4; i++) {
            int q = tid + i * 256; int row = q >> 3, seg = q & 7;
            cp16(s0 + row * PITCH + seg * 16,
                 Ap + (size_t)(tm + row) * K + kk + seg * 8);
        }
        uint32_t s1 = s0 + ATILE;
        #pragma unroll
        for (int i = 0; i < 4; i++) {
            int q = tid + i * 256; int row = q >> 3, seg = q & 7;
            cp16(s1 + row * PITCH + seg * 16,
                 Bp + (size_t)(tn + row) * K + kk + seg * 8);
        }
        cp_commit();
    };

    issue(0);

    const int lr16 = lane & 15, lh = (lane >> 4) * 16;

    for (int c = 0; c < NC; c++) {
        cp_wait<0>();
        __syncthreads();                   // single barrier per iteration
        if (c + 1 < NC) issue(c + 1);      // overwrites slot consumed at c-1 (safe)

        uint32_t aB = sb + (c & 1) * GBUF;
        uint32_t bB = aB + ATILE;

        #pragma unroll
        for (int k16 = 0; k16 < 4; k16++) {
            uint32_t koff = k16 * 32 + lh;
            uint32_t bf[2][4];
            #pragma unroll
            for (int pr = 0; pr < 2; pr++) {
                uint32_t addr = bB + (uint32_t)(wn + pr * 16 + lr16) * PITCH + koff;
                ldmx4(bf[pr][0], bf[pr][1], bf[pr][2], bf[pr][3], addr);
            }
            #pragma unroll
            for (int mi = 0; mi < 4; mi++) {
                uint32_t af[4];
                uint32_t addr = aB + (uint32_t)(wm + mi * 16 + lr16) * PITCH + koff;
                ldmx4(af[0], af[1], af[2], af[3], addr);
                #pragma unroll
                for (int ni = 0; ni < 4; ni++) {
                    uint32_t b0 = bf[ni >> 1][ni & 1];
                    uint32_t b1 = bf[ni >> 1][2 + (ni & 1)];
                    mma16816(acc[mi][ni], af, b0, b1);
                }
            }
        }
    }

    // ---------------- epilogue (register fragments -> GMEM) -------------
    const int qr = lane >> 2, qc = (lane & 3) * 2;
    #pragma unroll
    for (int mi = 0; mi < 4; mi++) {
        #pragma unroll
        for (int half = 0; half < 2; half++) {
            int r = tm + wm + mi * 16 + qr + half * 8;
            #pragma unroll
            for (int ni = 0; ni < 4; ni++) {
                int cc = tn + wn + ni * 8 + qc;
                float v0 = acc[mi][ni][half * 2 + 0];
                float v1 = acc[mi][ni][half * 2 + 1];
                if (EPI == 1) {
                    const float* p = extra + (size_t)(r & (SQ - 1)) * MM + cc;
                    v0 += p[0]; v1 += p[1];
                }
                if (EPI == 2) {
                    const float* p = extra + (size_t)r * Nc + cc;
                    v0 += p[0]; v1 += p[1];
                }
                if (EPI >= 3) { v0 += bias[cc]; v1 += bias[cc + 1]; }
                if (EPI == 3) {
                    v0 = 0.5f * v0 * (1.0f + erff(v0 * 0.70710678118654752f));
                    v1 = 0.5f * v1 * (1.0f + erff(v1 * 0.70710678118654752f));
                    __nv_bfloat16 h0 = __float2bfloat16(v0);
                    __nv_bfloat16 h1 = __float2bfloat16(v1);
                    __nv_bfloat162 hh; hh.x = h0; hh.y = h1;
                    *(__nv_bfloat162*)(Chi + (size_t)r * Nc + cc) = hh;
                    __nv_bfloat162 ll;
                    ll.x = __float2bfloat16(v0 - __bfloat162float(h0));
                    ll.y = __float2bfloat16(v1 - __bfloat162float(h1));
                    *(__nv_bfloat162*)(Clo + (size_t)r * Nc + cc) = ll;
                } else {
                    float2 t = make_float2(v0, v1);
                    *(float2*)(Cf + (size_t)r * Nc + cc) = t;
                }
            }
        }
    }
}

// ---------------- launcher ---------------------------------------------
extern "C" void kernel_launch(void* const* d_in, const int* in_sizes, int n_in,
                              void* d_out, int out_size)
{
    (void)in_sizes; (void)n_in; (void)out_size;
    const float* x      = (const float*)d_in[0];
    const float* weight = (const float*)d_in[1];
    // d_in[2]=Wq, d_in[3]=Wk: dead (softmax over size-1 axis == 1)
    const float* Wv     = (const float*)d_in[4];
    const float* Wo     = (const float*)d_in[5];
    const float* ln1_g  = (const float*)d_in[6];
    const float* ln1_b  = (const float*)d_in[7];
    const float* ln2_g  = (const float*)d_in[8];
    const float* ln2_b  = (const float*)d_in[9];
    const float* fc1_w  = (const float*)d_in[10];
    const float* fc1_b  = (const float*)d_in[11];
    const float* fc2_w  = (const float*)d_in[12];
    const float* fc2_b  = (const float*)d_in[13];
    float* out = (float*)d_out;

    float *s, *v, *pe;
    cudaGetSymbolAddress((void**)&s,  g_s);
    cudaGetSymbolAddress((void**)&v,  g_v);
    cudaGetSymbolAddress((void**)&pe, g_pe);
    __nv_bfloat16 *xh,*xl,*snh,*snl,*imh,*iml,*hh,*hl;
    __nv_bfloat16 *wh,*wl,*wvh,*wvl,*woh,*wol,*f1h,*f1l,*f2h,*f2l;
    cudaGetSymbolAddress((void**)&xh,  g_xh);  cudaGetSymbolAddress((void**)&xl,  g_xl);
    cudaGetSymbolAddress((void**)&snh, g_snh); cudaGetSymbolAddress((void**)&snl, g_snl);
    cudaGetSymbolAddress((void**)&imh, g_imh); cudaGetSymbolAddress((void**)&iml, g_iml);
    cudaGetSymbolAddress((void**)&hh,  g_hh);  cudaGetSymbolAddress((void**)&hl,  g_hl);
    cudaGetSymbolAddress((void**)&wh,  g_wh);  cudaGetSymbolAddress((void**)&wl,  g_wl);
    cudaGetSymbolAddress((void**)&wvh, g_wvh); cudaGetSymbolAddress((void**)&wvl, g_wvl);
    cudaGetSymbolAddress((void**)&woh, g_woh); cudaGetSymbolAddress((void**)&wol, g_wol);
    cudaGetSymbolAddress((void**)&f1h, g_f1h); cudaGetSymbolAddress((void**)&f1l, g_f1l);
    cudaGetSymbolAddress((void**)&f2h, g_f2h); cudaGetSymbolAddress((void**)&f2l, g_f2l);

    cudaFuncSetAttribute(hmma_gemm<0>, cudaFuncAttributeMaxDynamicSharedMemorySize, SMEMB);
    cudaFuncSetAttribute(hmma_gemm<1>, cudaFuncAttributeMaxDynamicSharedMemorySize, SMEMB);
    cudaFuncSetAttribute(hmma_gemm<2>, cudaFuncAttributeMaxDynamicSharedMemorySize, SMEMB);
    cudaFuncSetAttribute(hmma_gemm<3>, cudaFuncAttributeMaxDynamicSharedMemorySize, SMEMB);
    cudaFuncSetAttribute(hmma_gemm<4>, cudaFuncAttributeMaxDynamicSharedMemorySize, SMEMB);

    dim3 g768(MM / 128, ROWS / 128);    // (6, 32)
    dim3 g3072(HID / 128, ROWS / 128);  // (24, 32)

    // launches 1-3: fused preps (so launch #6 below is a GEMM for ncu -s 5)
    prep_a<<<1024, 256>>>(x, xh, xl, weight, wh, wl, pe);
    prep_pair<<<1024, 256>>>(Wv, wvh, wvl, Wo, woh, wol, TK * MM * MM);
    prep_pair<<<1024, 256>>>(fc1_w, f1h, f1l, fc2_w, f2h, f2l, HID * MM);

    // launch 4: prelude s = x @ weight^T + PE
    hmma_gemm<1><<<g768, 256, SMEMB>>>(xh, xl, wh, wl, nullptr, pe,
                                       s, nullptr, nullptr, MM, MM);

    for (int a = 0; a < TK; a++) {
        size_t off = (size_t)a * MM * MM;
        // launch 5 (a=0): sn = LN1(s)
        ln_split_kernel<false><<<ROWS, 256>>>(s, ln1_g, ln1_b, snh, snl);
        // launch 6 (a=0): v = sn @ Wv[a]^T  <-- ncu profiles this
        hmma_gemm<0><<<g768, 256, SMEMB>>>(snh, snl, wvh + off, wvl + off,
                                           nullptr, nullptr, v, nullptr, nullptr, MM, MM);
        // imv = exclusive cumsum over tokens
        scan_split_kernel<<<(NB * MM) / 256, 256>>>(v, imh, iml);
        // s = imv @ Wo[a]^T + s
        hmma_gemm<2><<<g768, 256, SMEMB>>>(imh, iml, woh + off, wol + off,
                                           nullptr, s, s, nullptr, nullptr, MM, MM);
        // t = LN2(s) + s
        ln_split_kernel<true><<<ROWS, 256>>>(s, ln2_g, ln2_b, snh, snl);
        // h = GELU(t @ fc1^T + b1)
        hmma_gemm<3><<<g3072, 256, SMEMB>>>(snh, snl, f1h, f1l, fc1_b, nullptr,
                                            nullptr, hh, hl, HID, MM);
        // s = h @ fc2^T + b2 (last stage -> d_out)
        float* dst = (a == TK - 1) ? out : s;
        hmma_gemm<4><<<g768, 256, SMEMB>>>(hh, hl, f2h, f2l, fc2_b, nullptr,
                                           dst, nullptr, nullptr, MM, HID);
    }
}

// round 11
// speedup vs baseline: 1.4823x; 1.4823x over previous
#include <cuda_runtime.h>
#include <cuda_bf16.h>
#include <math.h>
#include <stdint.h>

#define NB   16
#define SQ   256
#define MM   768
#define TK   10
#define ROWS (NB*SQ)        // 4096
#define HID  (4*MM)         // 3072
#define EPS  1e-5f

// ---------------- static scratch (allocation-free rule) ----------------
__device__ float g_s [ROWS*MM];
__device__ float g_v [ROWS*MM];
__device__ float g_pe[SQ*MM];

__device__ __nv_bfloat16 g_xh [ROWS*MM],  g_xl [ROWS*MM];
__device__ __nv_bfloat16 g_snh[ROWS*MM],  g_snl[ROWS*MM];
__device__ __nv_bfloat16 g_imh[ROWS*MM],  g_iml[ROWS*MM];
__device__ __nv_bfloat16 g_hh [ROWS*HID], g_hl [ROWS*HID];

__device__ __nv_bfloat16 g_wh [MM*MM],      g_wl [MM*MM];
__device__ __nv_bfloat16 g_wvh[TK*MM*MM],   g_wvl[TK*MM*MM];
__device__ __nv_bfloat16 g_woh[TK*MM*MM],   g_wol[TK*MM*MM];
__device__ __nv_bfloat16 g_f1h[HID*MM],     g_f1l[HID*MM];
__device__ __nv_bfloat16 g_f2h[MM*HID],     g_f2l[MM*HID];

// ---------------- small helpers ----------------------------------------
__device__ __forceinline__ uint32_t s2u(const void* p) {
    uint32_t a;
    asm("{ .reg .u64 t; cvta.to.shared.u64 t, %1; cvt.u32.u64 %0, t; }"
        : "=r"(a) : "l"(p));
    return a;
}
__device__ __forceinline__ void cp16(uint32_t sdst, const void* gsrc) {
    asm volatile("cp.async.cg.shared.global [%0], [%1], 16;"
                 :: "r"(sdst), "l"(gsrc) : "memory");
}
__device__ __forceinline__ void cp_commit() {
    asm volatile("cp.async.commit_group;" ::: "memory");
}
template <int N>
__device__ __forceinline__ void cp_wait() {
    asm volatile("cp.async.wait_group %0;" :: "n"(N) : "memory");
}
__device__ __forceinline__ void ldmx4(uint32_t& r0, uint32_t& r1,
                                      uint32_t& r2, uint32_t& r3, uint32_t a) {
    asm volatile("ldmatrix.sync.aligned.m8n8.x4.shared.b16 {%0,%1,%2,%3}, [%4];"
                 : "=r"(r0), "=r"(r1), "=r"(r2), "=r"(r3) : "r"(a));
}
__device__ __forceinline__ void mma16816(float* d, const uint32_t* a,
                                         uint32_t b0, uint32_t b1) {
    asm volatile("mma.sync.aligned.m16n8k16.row.col.f32.bf16.bf16.f32 "
                 "{%0,%1,%2,%3}, {%4,%5,%6,%7}, {%8,%9}, {%0,%1,%2,%3};"
                 : "+f"(d[0]), "+f"(d[1]), "+f"(d[2]), "+f"(d[3])
                 : "r"(a[0]), "r"(a[1]), "r"(a[2]), "r"(a[3]),
                   "r"(b0), "r"(b1));
}
__device__ __forceinline__ void split1(float x, __nv_bfloat16* h, __nv_bfloat16* l) {
    __nv_bfloat16 hi = __float2bfloat16(x);
    *h = hi;
    *l = __float2bfloat16(x - __bfloat162float(hi));
}

// ---------------- prep kernels (fused: fewer launches, aligns ncu) ------
__global__ __launch_bounds__(256) void prep_a(
    const float* __restrict__ x, __nv_bfloat16* __restrict__ xh, __nv_bfloat16* __restrict__ xl,
    const float* __restrict__ w, __nv_bfloat16* __restrict__ wh, __nv_bfloat16* __restrict__ wl,
    float* __restrict__ pe)
{
    int stride = gridDim.x * blockDim.x;
    int t = blockIdx.x * blockDim.x + threadIdx.x;
    for (int i = t; i < ROWS * MM; i += stride) split1(x[i], xh + i, xl + i);
    for (int i = t; i < MM * MM; i += stride)   split1(w[i], wh + i, wl + i);
    for (int i = t; i < SQ * MM; i += stride) {
        int j = i / MM, m = i % MM, z = m & ~1;
        double ang = (double)j * exp(-((double)(2 * z) / (double)MM) * log(10000.0));
        pe[i] = (float)((m & 1) ? cos(ang) : sin(ang));
    }
}
__global__ __launch_bounds__(256) void prep_pair(
    const float* __restrict__ a, __nv_bfloat16* __restrict__ ah, __nv_bfloat16* __restrict__ al,
    const float* __restrict__ b, __nv_bfloat16* __restrict__ bh, __nv_bfloat16* __restrict__ bl,
    int n)
{
    int stride = gridDim.x * blockDim.x;
    int t = blockIdx.x * blockDim.x + threadIdx.x;
    for (int i = t; i < n; i += stride) {
        split1(a[i], ah + i, al + i);
        split1(b[i], bh + i, bl + i);
    }
}

// ---------------- LayerNorm (+optional residual) -> hi/lo bf16 ---------
template <bool ADDRES>
__global__ __launch_bounds__(256) void ln_split_kernel(
    const float* __restrict__ in, const float* __restrict__ g,
    const float* __restrict__ b, __nv_bfloat16* __restrict__ oh,
    __nv_bfloat16* __restrict__ ol)
{
    int r = blockIdx.x;
    int tid = threadIdx.x;
    const float* row = in + (size_t)r * MM;
    float x0 = row[tid], x1 = row[tid + 256], x2 = row[tid + 512];

    __shared__ float sd[256];
    sd[tid] = x0 + x1 + x2;
    __syncthreads();
    #pragma unroll
    for (int o = 128; o > 0; o >>= 1) { if (tid < o) sd[tid] += sd[tid + o]; __syncthreads(); }
    float mu = sd[0] * (1.0f / (float)MM);
    __syncthreads();

    float d0 = x0 - mu, d1 = x1 - mu, d2 = x2 - mu;
    sd[tid] = d0 * d0 + d1 * d1 + d2 * d2;
    __syncthreads();
    #pragma unroll
    for (int o = 128; o > 0; o >>= 1) { if (tid < o) sd[tid] += sd[tid + o]; __syncthreads(); }
    float rstd = rsqrtf(sd[0] * (1.0f / (float)MM) + EPS);

    size_t base = (size_t)r * MM;
    float v0 = d0 * rstd * g[tid]       + b[tid]       + (ADDRES ? x0 : 0.f);
    float v1 = d1 * rstd * g[tid + 256] + b[tid + 256] + (ADDRES ? x1 : 0.f);
    float v2 = d2 * rstd * g[tid + 512] + b[tid + 512] + (ADDRES ? x2 : 0.f);
    split1(v0, oh + base + tid,       ol + base + tid);
    split1(v1, oh + base + tid + 256, ol + base + tid + 256);
    split1(v2, oh + base + tid + 512, ol + base + tid + 512);
}

// ---------------- exclusive token prefix sum -> hi/lo bf16 -------------
__global__ __launch_bounds__(256) void scan_split_kernel(
    const float* __restrict__ v, __nv_bfloat16* __restrict__ oh,
    __nv_bfloat16* __restrict__ ol)
{
    int idx = blockIdx.x * 256 + threadIdx.x;     // 0..12287 = (n,d)
    int n = idx / MM;
    int d = idx % MM;
    const float* src = v + (size_t)n * SQ * MM + d;
    size_t base = (size_t)n * SQ * MM + d;
    float acc = 0.f;
    #pragma unroll 8
    for (int j = 0; j < SQ; j++) {
        __nv_bfloat16 h = __float2bfloat16(acc);
        oh[base + (size_t)j * MM] = h;
        ol[base + (size_t)j * MM] = __float2bfloat16(acc - __bfloat162float(h));
        acc += src[(size_t)j * MM];
    }
}

// ---------------- HMMA GEMM: C = A @ W^T, bf16x3 split ------------------
// CTA tile 128x64, BK=32, 8 warps (32x32 each, 4x2 layout), ~80 regs ->
// 3 CTAs/SM. 2-stage cp.async pipeline (R9-proven: issue-ahead + wait<1>,
// two barriers). SMEM pitch 80B -> conflict-free ldmatrix phases.
// EPI: 0 = fp32; 1 = fp32+PE; 2 = fp32+residual; 3 = bias+GELU->hi/lo; 4 = fp32+bias.
#define PITCH  80
#define STAGE  (192 * PITCH)          // A(128 rows) + B(64 rows) = 15360 B

template <int EPI>
__global__ __launch_bounds__(256, 3) void hmma_gemm(
    const __nv_bfloat16* __restrict__ Ah, const __nv_bfloat16* __restrict__ Al,
    const __nv_bfloat16* __restrict__ Wh, const __nv_bfloat16* __restrict__ Wl,
    const float* __restrict__ bias, const float* __restrict__ extra,
    float* __restrict__ Cf, __nv_bfloat16* __restrict__ Chi,
    __nv_bfloat16* __restrict__ Clo, int Nc, int K)
{
    __shared__ __align__(16) char smem[2 * STAGE];   // 30720 B
    const uint32_t sb = s2u(smem);
    const int tid = threadIdx.x, wid = tid >> 5, lane = tid & 31;
    const int tm = blockIdx.y * 128, tn = blockIdx.x * 64;
    const int wm = (wid & 3) * 32;       // warp row offset (4 groups)
    const int wn = (wid >> 2) * 32;      // warp col offset (2 groups)

    const int KC = K / 32;               // chunks per pass
    const int NC = 3 * KC;               // total chunks (3 split passes)

    float acc[2][4][4];
    #pragma unroll
    for (int i = 0; i < 2; i++)
        #pragma unroll
        for (int j = 0; j < 4; j++)
            #pragma unroll
            for (int t = 0; t < 4; t++) acc[i][j][t] = 0.f;

    // 768 cp16 per chunk (A: 512, B: 256) -> 3 per thread
    auto issue = [&](int c) {
        int pass = c / KC;
        int kk = (c - pass * KC) * 32;
        const __nv_bfloat16* Ap = (pass == 2) ? Al : Ah;
        const __nv_bfloat16* Bp = (pass == 1) ? Wl : Wh;
        uint32_t s0 = sb + (c & 1) * STAGE;
        #pragma unroll
        for (int i = 0; i < 3; i++) {
            int q = tid + i * 256;
            int row = q >> 2, seg = q & 3;
            const __nv_bfloat16* src = (row < 128)
                ? Ap + (size_t)(tm + row) * K + kk + seg * 8
                : Bp + (size_t)(tn + row - 128) * K + kk + seg * 8;
            cp16(s0 + row * PITCH + seg * 16, src);
        }
        cp_commit();
    };

    issue(0);

    const int lr16 = lane & 15, lh = (lane >> 4) * 16;

    for (int c = 0; c < NC; c++) {
        if (c + 1 < NC) { issue(c + 1); cp_wait<1>(); }
        else            { cp_wait<0>(); }
        __syncthreads();

        uint32_t aB = sb + (c & 1) * STAGE;
        uint32_t bB = aB + 128 * PITCH;

        #pragma unroll
        for (int k16 = 0; k16 < 2; k16++) {
            uint32_t koff = k16 * 32 + lh;
            // B fragments: 2 x ldmatrix.x4 (16 n-rows each)
            uint32_t bf[2][4];
            #pragma unroll
            for (int pr = 0; pr < 2; pr++) {
                uint32_t addr = bB + (uint32_t)(wn + pr * 16 + lr16) * PITCH + koff;
                ldmx4(bf[pr][0], bf[pr][1], bf[pr][2], bf[pr][3], addr);
            }
            // A fragments + MMAs: 2 m-tiles of 16 rows
            #pragma unroll
            for (int mi = 0; mi < 2; mi++) {
                uint32_t af[4];
                uint32_t addr = aB + (uint32_t)(wm + mi * 16 + lr16) * PITCH + koff;
                ldmx4(af[0], af[1], af[2], af[3], addr);
                #pragma unroll
                for (int ni = 0; ni < 4; ni++) {
                    uint32_t b0 = bf[ni >> 1][ni & 1];
                    uint32_t b1 = bf[ni >> 1][2 + (ni & 1)];
                    mma16816(acc[mi][ni], af, b0, b1);
                }
            }
        }
        __syncthreads();
    }

    // ---------------- epilogue (register fragments -> GMEM) -------------
    const int qr = lane >> 2, qc = (lane & 3) * 2;
    #pragma unroll
    for (int mi = 0; mi < 2; mi++) {
        #pragma unroll
        for (int half = 0; half < 2; half++) {
            int r = tm + wm + mi * 16 + qr + half * 8;
            #pragma unroll
            for (int ni = 0; ni < 4; ni++) {
                int cc = tn + wn + ni * 8 + qc;
                float v0 = acc[mi][ni][half * 2 + 0];
                float v1 = acc[mi][ni][half * 2 + 1];
                if (EPI == 1) {
                    const float* p = extra + (size_t)(r & (SQ - 1)) * MM + cc;
                    v0 += p[0]; v1 += p[1];
                }
                if (EPI == 2) {
                    const float* p = extra + (size_t)r * Nc + cc;
                    v0 += p[0]; v1 += p[1];
                }
                if (EPI >= 3) { v0 += bias[cc]; v1 += bias[cc + 1]; }
                if (EPI == 3) {
                    v0 = 0.5f * v0 * (1.0f + erff(v0 * 0.70710678118654752f));
                    v1 = 0.5f * v1 * (1.0f + erff(v1 * 0.70710678118654752f));
                    __nv_bfloat16 h0 = __float2bfloat16(v0);
                    __nv_bfloat16 h1 = __float2bfloat16(v1);
                    __nv_bfloat162 hh; hh.x = h0; hh.y = h1;
                    *(__nv_bfloat162*)(Chi + (size_t)r * Nc + cc) = hh;
                    __nv_bfloat162 ll;
                    ll.x = __float2bfloat16(v0 - __bfloat162float(h0));
                    ll.y = __float2bfloat16(v1 - __bfloat162float(h1));
                    *(__nv_bfloat162*)(Clo + (size_t)r * Nc + cc) = ll;
                } else {
                    float2 t = make_float2(v0, v1);
                    *(float2*)(Cf + (size_t)r * Nc + cc) = t;
                }
            }
        }
    }
}

// ---------------- launcher ---------------------------------------------
extern "C" void kernel_launch(void* const* d_in, const int* in_sizes, int n_in,
                              void* d_out, int out_size)
{
    (void)in_sizes; (void)n_in; (void)out_size;
    const float* x      = (const float*)d_in[0];
    const float* weight = (const float*)d_in[1];
    // d_in[2]=Wq, d_in[3]=Wk: dead (softmax over size-1 axis == 1)
    const float* Wv     = (const float*)d_in[4];
    const float* Wo     = (const float*)d_in[5];
    const float* ln1_g  = (const float*)d_in[6];
    const float* ln1_b  = (const float*)d_in[7];
    const float* ln2_g  = (const float*)d_in[8];
    const float* ln2_b  = (const float*)d_in[9];
    const float* fc1_w  = (const float*)d_in[10];
    const float* fc1_b  = (const float*)d_in[11];
    const float* fc2_w  = (const float*)d_in[12];
    const float* fc2_b  = (const float*)d_in[13];
    float* out = (float*)d_out;

    float *s, *v, *pe;
    cudaGetSymbolAddress((void**)&s,  g_s);
    cudaGetSymbolAddress((void**)&v,  g_v);
    cudaGetSymbolAddress((void**)&pe, g_pe);
    __nv_bfloat16 *xh,*xl,*snh,*snl,*imh,*iml,*hh,*hl;
    __nv_bfloat16 *wh,*wl,*wvh,*wvl,*woh,*wol,*f1h,*f1l,*f2h,*f2l;
    cudaGetSymbolAddress((void**)&xh,  g_xh);  cudaGetSymbolAddress((void**)&xl,  g_xl);
    cudaGetSymbolAddress((void**)&snh, g_snh); cudaGetSymbolAddress((void**)&snl, g_snl);
    cudaGetSymbolAddress((void**)&imh, g_imh); cudaGetSymbolAddress((void**)&iml, g_iml);
    cudaGetSymbolAddress((void**)&hh,  g_hh);  cudaGetSymbolAddress((void**)&hl,  g_hl);
    cudaGetSymbolAddress((void**)&wh,  g_wh);  cudaGetSymbolAddress((void**)&wl,  g_wl);
    cudaGetSymbolAddress((void**)&wvh, g_wvh); cudaGetSymbolAddress((void**)&wvl, g_wvl);
    cudaGetSymbolAddress((void**)&woh, g_woh); cudaGetSymbolAddress((void**)&wol, g_wol);
    cudaGetSymbolAddress((void**)&f1h, g_f1h); cudaGetSymbolAddress((void**)&f1l, g_f1l);
    cudaGetSymbolAddress((void**)&f2h, g_f2h); cudaGetSymbolAddress((void**)&f2l, g_f2l);

    dim3 g768(MM / 64, ROWS / 128);    // (12, 32) = 384 CTAs
    dim3 g3072(HID / 64, ROWS / 128);  // (48, 32) = 1536 CTAs

    // launches 1-3: fused preps (launch #6 below = Wv GEMM for ncu -s 5)
    prep_a<<<1024, 256>>>(x, xh, xl, weight, wh, wl, pe);
    prep_pair<<<1024, 256>>>(Wv, wvh, wvl, Wo, woh, wol, TK * MM * MM);
    prep_pair<<<1024, 256>>>(fc1_w, f1h, f1l, fc2_w, f2h, f2l, HID * MM);

    // launch 4: prelude s = x @ weight^T + PE
    hmma_gemm<1><<<g768, 256>>>(xh, xl, wh, wl, nullptr, pe,
                                s, nullptr, nullptr, MM, MM);

    for (int a = 0; a < TK; a++) {
        size_t off = (size_t)a * MM * MM;
        // sn = LN1(s)
        ln_split_kernel<false><<<ROWS, 256>>>(s, ln1_g, ln1_b, snh, snl);
        // v = sn @ Wv[a]^T   <-- launch #6 on a=0 (ncu profiles this)
        hmma_gemm<0><<<g768, 256>>>(snh, snl, wvh + off, wvl + off,
                                    nullptr, nullptr, v, nullptr, nullptr, MM, MM);
        // imv = exclusive cumsum over tokens
        scan_split_kernel<<<(NB * MM) / 256, 256>>>(v, imh, iml);
        // s = imv @ Wo[a]^T + s
        hmma_gemm<2><<<g768, 256>>>(imh, iml, woh + off, wol + off,
                                    nullptr, s, s, nullptr, nullptr, MM, MM);
        // t = LN2(s) + s
        ln_split_kernel<true><<<ROWS, 256>>>(s, ln2_g, ln2_b, snh, snl);
        // h = GELU(t @ fc1^T + b1)
        hmma_gemm<3><<<g3072, 256>>>(snh, snl, f1h, f1l, fc1_b, nullptr,
                                     nullptr, hh, hl, HID, MM);
        // s = h @ fc2^T + b2 (last stage -> d_out)
        float* dst = (a == TK - 1) ? out : s;
        hmma_gemm<4><<<g768, 256>>>(hh, hl, f2h, f2l, fc2_b, nullptr,
                                    dst, nullptr, nullptr, MM, HID);
    }
}

// round 12
// speedup vs baseline: 1.7021x; 1.1483x over previous
#include <cuda_runtime.h>
#include <cuda_bf16.h>
#include <math.h>
#include <stdint.h>

#define NB   16
#define SQ   256
#define MM   768
#define TK   10
#define ROWS (NB*SQ)        // 4096
#define HID  (4*MM)         // 3072
#define EPS  1e-5f

// ---------------- static scratch (allocation-free rule) ----------------
__device__ float g_s [ROWS*MM];
__device__ float g_v [ROWS*MM];
__device__ float g_pe[SQ*MM];

__device__ __nv_bfloat16 g_xh [ROWS*MM],  g_xl [ROWS*MM];
__device__ __nv_bfloat16 g_snh[ROWS*MM],  g_snl[ROWS*MM];
__device__ __nv_bfloat16 g_imh[ROWS*MM],  g_iml[ROWS*MM];
__device__ __nv_bfloat16 g_hh [ROWS*HID], g_hl [ROWS*HID];

__device__ __nv_bfloat16 g_wh [MM*MM],      g_wl [MM*MM];
__device__ __nv_bfloat16 g_wvh[TK*MM*MM],   g_wvl[TK*MM*MM];
__device__ __nv_bfloat16 g_woh[TK*MM*MM],   g_wol[TK*MM*MM];
__device__ __nv_bfloat16 g_f1h[HID*MM],     g_f1l[HID*MM];
__device__ __nv_bfloat16 g_f2h[MM*HID],     g_f2l[MM*HID];

// ---------------- small helpers ----------------------------------------
__device__ __forceinline__ uint32_t s2u(const void* p) {
    uint32_t a;
    asm("{ .reg .u64 t; cvta.to.shared.u64 t, %1; cvt.u32.u64 %0, t; }"
        : "=r"(a) : "l"(p));
    return a;
}
__device__ __forceinline__ void cp16(uint32_t sdst, const void* gsrc) {
    asm volatile("cp.async.cg.shared.global [%0], [%1], 16;"
                 :: "r"(sdst), "l"(gsrc) : "memory");
}
__device__ __forceinline__ void cp_commit() {
    asm volatile("cp.async.commit_group;" ::: "memory");
}
template <int N>
__device__ __forceinline__ void cp_wait() {
    asm volatile("cp.async.wait_group %0;" :: "n"(N) : "memory");
}
__device__ __forceinline__ void ldmx4(uint32_t& r0, uint32_t& r1,
                                      uint32_t& r2, uint32_t& r3, uint32_t a) {
    asm volatile("ldmatrix.sync.aligned.m8n8.x4.shared.b16 {%0,%1,%2,%3}, [%4];"
                 : "=r"(r0), "=r"(r1), "=r"(r2), "=r"(r3) : "r"(a));
}
__device__ __forceinline__ void mma16816(float* d, const uint32_t* a,
                                         uint32_t b0, uint32_t b1) {
    asm volatile("mma.sync.aligned.m16n8k16.row.col.f32.bf16.bf16.f32 "
                 "{%0,%1,%2,%3}, {%4,%5,%6,%7}, {%8,%9}, {%0,%1,%2,%3};"
                 : "+f"(d[0]), "+f"(d[1]), "+f"(d[2]), "+f"(d[3])
                 : "r"(a[0]), "r"(a[1]), "r"(a[2]), "r"(a[3]),
                   "r"(b0), "r"(b1));
}
__device__ __forceinline__ void split1(float x, __nv_bfloat16* h, __nv_bfloat16* l) {
    __nv_bfloat16 hi = __float2bfloat16(x);
    *h = hi;
    *l = __float2bfloat16(x - __bfloat162float(hi));
}

// ---------------- prep kernels (fused: fewer launches, aligns ncu) ------
__global__ __launch_bounds__(256) void prep_a(
    const float* __restrict__ x, __nv_bfloat16* __restrict__ xh, __nv_bfloat16* __restrict__ xl,
    const float* __restrict__ w, __nv_bfloat16* __restrict__ wh, __nv_bfloat16* __restrict__ wl,
    float* __restrict__ pe)
{
    int stride = gridDim.x * blockDim.x;
    int t = blockIdx.x * blockDim.x + threadIdx.x;
    for (int i = t; i < ROWS * MM; i += stride) split1(x[i], xh + i, xl + i);
    for (int i = t; i < MM * MM; i += stride)   split1(w[i], wh + i, wl + i);
    for (int i = t; i < SQ * MM; i += stride) {
        int j = i / MM, m = i % MM, z = m & ~1;
        double ang = (double)j * exp(-((double)(2 * z) / (double)MM) * log(10000.0));
        pe[i] = (float)((m & 1) ? cos(ang) : sin(ang));
    }
}
__global__ __launch_bounds__(256) void prep_pair(
    const float* __restrict__ a, __nv_bfloat16* __restrict__ ah, __nv_bfloat16* __restrict__ al,
    const float* __restrict__ b, __nv_bfloat16* __restrict__ bh, __nv_bfloat16* __restrict__ bl,
    int n)
{
    int stride = gridDim.x * blockDim.x;
    int t = blockIdx.x * blockDim.x + threadIdx.x;
    for (int i = t; i < n; i += stride) {
        split1(a[i], ah + i, al + i);
        split1(b[i], bh + i, bl + i);
    }
}

// ---------------- LayerNorm (+optional residual) -> hi/lo bf16 ---------
template <bool ADDRES>
__global__ __launch_bounds__(256) void ln_split_kernel(
    const float* __restrict__ in, const float* __restrict__ g,
    const float* __restrict__ b, __nv_bfloat16* __restrict__ oh,
    __nv_bfloat16* __restrict__ ol)
{
    int r = blockIdx.x;
    int tid = threadIdx.x;
    const float* row = in + (size_t)r * MM;
    float x0 = row[tid], x1 = row[tid + 256], x2 = row[tid + 512];

    __shared__ float sd[256];
    sd[tid] = x0 + x1 + x2;
    __syncthreads();
    #pragma unroll
    for (int o = 128; o > 0; o >>= 1) { if (tid < o) sd[tid] += sd[tid + o]; __syncthreads(); }
    float mu = sd[0] * (1.0f / (float)MM);
    __syncthreads();

    float d0 = x0 - mu, d1 = x1 - mu, d2 = x2 - mu;
    sd[tid] = d0 * d0 + d1 * d1 + d2 * d2;
    __syncthreads();
    #pragma unroll
    for (int o = 128; o > 0; o >>= 1) { if (tid < o) sd[tid] += sd[tid + o]; __syncthreads(); }
    float rstd = rsqrtf(sd[0] * (1.0f / (float)MM) + EPS);

    size_t base = (size_t)r * MM;
    float v0 = d0 * rstd * g[tid]       + b[tid]       + (ADDRES ? x0 : 0.f);
    float v1 = d1 * rstd * g[tid + 256] + b[tid + 256] + (ADDRES ? x1 : 0.f);
    float v2 = d2 * rstd * g[tid + 512] + b[tid + 512] + (ADDRES ? x2 : 0.f);
    split1(v0, oh + base + tid,       ol + base + tid);
    split1(v1, oh + base + tid + 256, ol + base + tid + 256);
    split1(v2, oh + base + tid + 512, ol + base + tid + 512);
}

// ---------------- exclusive token prefix sum -> hi/lo bf16 -------------
__global__ __launch_bounds__(256) void scan_split_kernel(
    const float* __restrict__ v, __nv_bfloat16* __restrict__ oh,
    __nv_bfloat16* __restrict__ ol)
{
    int idx = blockIdx.x * 256 + threadIdx.x;     // 0..12287 = (n,d)
    int n = idx / MM;
    int d = idx % MM;
    const float* src = v + (size_t)n * SQ * MM + d;
    size_t base = (size_t)n * SQ * MM + d;
    float acc = 0.f;
    #pragma unroll 8
    for (int j = 0; j < SQ; j++) {
        __nv_bfloat16 h = __float2bfloat16(acc);
        oh[base + (size_t)j * MM] = h;
        ol[base + (size_t)j * MM] = __float2bfloat16(acc - __bfloat162float(h));
        acc += src[(size_t)j * MM];
    }
}

// ---------------- HMMA GEMM: C = A @ W^T, bf16x3 split ------------------
// CTA tile 128x64, BK=64, 8 warps (32x32 each), ~80 regs -> 3 CTAs/SM.
// Dynamic smem: 2 stages x 27648B = 55296B (3 CTAs x 55.3KB = 166KB < 227KB,
// so regs remain the occupancy limiter). 2-stage cp.async pipeline
// (issue-ahead + wait<1>). Pitch 144B -> conflict-free ldmatrix phases.
// Per chunk: 32 MMAs + 12 ldmatrix between barrier pairs (2x R11).
// EPI: 0 = fp32; 1 = fp32+PE; 2 = fp32+residual; 3 = bias+GELU->hi/lo; 4 = fp32+bias.
#define PITCH  144
#define STAGE  (192 * PITCH)          // A(128 rows) + B(64 rows) = 27648 B
#define SMEMB  (2 * STAGE)            // 55296 B

template <int EPI>
__global__ __launch_bounds__(256, 3) void hmma_gemm(
    const __nv_bfloat16* __restrict__ Ah, const __nv_bfloat16* __restrict__ Al,
    const __nv_bfloat16* __restrict__ Wh, const __nv_bfloat16* __restrict__ Wl,
    const float* __restrict__ bias, const float* __restrict__ extra,
    float* __restrict__ Cf, __nv_bfloat16* __restrict__ Chi,
    __nv_bfloat16* __restrict__ Clo, int Nc, int K)
{
    extern __shared__ __align__(16) char smem[];
    const uint32_t sb = s2u(smem);
    const int tid = threadIdx.x, wid = tid >> 5, lane = tid & 31;
    const int tm = blockIdx.y * 128, tn = blockIdx.x * 64;
    const int wm = (wid & 3) * 32;       // warp row offset (4 groups)
    const int wn = (wid >> 2) * 32;      // warp col offset (2 groups)

    const int KC = K / 64;               // chunks per pass
    const int NC = 3 * KC;               // total chunks (3 split passes)

    float acc[2][4][4];
    #pragma unroll
    for (int i = 0; i < 2; i++)
        #pragma unroll
        for (int j = 0; j < 4; j++)
            #pragma unroll
            for (int t = 0; t < 4; t++) acc[i][j][t] = 0.f;

    // 1536 cp16 per chunk (A: 1024, B: 512) -> 6 per thread
    auto issue = [&](int c) {
        int pass = c / KC;
        int kk = (c - pass * KC) * 64;
        const __nv_bfloat16* Ap = (pass == 2) ? Al : Ah;
        const __nv_bfloat16* Bp = (pass == 1) ? Wl : Wh;
        uint32_t s0 = sb + (c & 1) * STAGE;
        #pragma unroll
        for (int i = 0; i < 6; i++) {
            int q = tid + i * 256;
            int row = q >> 3, seg = q & 7;
            const __nv_bfloat16* src = (row < 128)
                ? Ap + (size_t)(tm + row) * K + kk + seg * 8
                : Bp + (size_t)(tn + row - 128) * K + kk + seg * 8;
            cp16(s0 + row * PITCH + seg * 16, src);
        }
        cp_commit();
    };

    issue(0);

    const int lr16 = lane & 15, lh = (lane >> 4) * 16;

    for (int c = 0; c < NC; c++) {
        if (c + 1 < NC) { issue(c + 1); cp_wait<1>(); }
        else            { cp_wait<0>(); }
        __syncthreads();

        uint32_t aB = sb + (c & 1) * STAGE;
        uint32_t bB = aB + 128 * PITCH;

        #pragma unroll
        for (int k16 = 0; k16 < 4; k16++) {
            uint32_t koff = k16 * 32 + lh;
            // B fragments: 2 x ldmatrix.x4 (16 n-rows each)
            uint32_t bf[2][4];
            #pragma unroll
            for (int pr = 0; pr < 2; pr++) {
                uint32_t addr = bB + (uint32_t)(wn + pr * 16 + lr16) * PITCH + koff;
                ldmx4(bf[pr][0], bf[pr][1], bf[pr][2], bf[pr][3], addr);
            }
            // A fragments + MMAs: 2 m-tiles of 16 rows
            #pragma unroll
            for (int mi = 0; mi < 2; mi++) {
                uint32_t af[4];
                uint32_t addr = aB + (uint32_t)(wm + mi * 16 + lr16) * PITCH + koff;
                ldmx4(af[0], af[1], af[2], af[3], addr);
                #pragma unroll
                for (int ni = 0; ni < 4; ni++) {
                    uint32_t b0 = bf[ni >> 1][ni & 1];
                    uint32_t b1 = bf[ni >> 1][2 + (ni & 1)];
                    mma16816(acc[mi][ni], af, b0, b1);
                }
            }
        }
        __syncthreads();
    }

    // ---------------- epilogue (register fragments -> GMEM) -------------
    const int qr = lane >> 2, qc = (lane & 3) * 2;
    #pragma unroll
    for (int mi = 0; mi < 2; mi++) {
        #pragma unroll
        for (int half = 0; half < 2; half++) {
            int r = tm + wm + mi * 16 + qr + half * 8;
            #pragma unroll
            for (int ni = 0; ni < 4; ni++) {
                int cc = tn + wn + ni * 8 + qc;
                float v0 = acc[mi][ni][half * 2 + 0];
                float v1 = acc[mi][ni][half * 2 + 1];
                if (EPI == 1) {
                    const float* p = extra + (size_t)(r & (SQ - 1)) * MM + cc;
                    v0 += p[0]; v1 += p[1];
                }
                if (EPI == 2) {
                    const float* p = extra + (size_t)r * Nc + cc;
                    v0 += p[0]; v1 += p[1];
                }
                if (EPI >= 3) { v0 += bias[cc]; v1 += bias[cc + 1]; }
                if (EPI == 3) {
                    v0 = 0.5f * v0 * (1.0f + erff(v0 * 0.70710678118654752f));
                    v1 = 0.5f * v1 * (1.0f + erff(v1 * 0.70710678118654752f));
                    __nv_bfloat16 h0 = __float2bfloat16(v0);
                    __nv_bfloat16 h1 = __float2bfloat16(v1);
                    __nv_bfloat162 hh; hh.x = h0; hh.y = h1;
                    *(__nv_bfloat162*)(Chi + (size_t)r * Nc + cc) = hh;
                    __nv_bfloat162 ll;
                    ll.x = __float2bfloat16(v0 - __bfloat162float(h0));
                    ll.y = __float2bfloat16(v1 - __bfloat162float(h1));
                    *(__nv_bfloat162*)(Clo + (size_t)r * Nc + cc) = ll;
                } else {
                    float2 t = make_float2(v0, v1);
                    *(float2*)(Cf + (size_t)r * Nc + cc) = t;
                }
            }
        }
    }
}

// ---------------- launcher ---------------------------------------------
extern "C" void kernel_launch(void* const* d_in, const int* in_sizes, int n_in,
                              void* d_out, int out_size)
{
    (void)in_sizes; (void)n_in; (void)out_size;
    const float* x      = (const float*)d_in[0];
    const float* weight = (const float*)d_in[1];
    // d_in[2]=Wq, d_in[3]=Wk: dead (softmax over size-1 axis == 1)
    const float* Wv     = (const float*)d_in[4];
    const float* Wo     = (const float*)d_in[5];
    const float* ln1_g  = (const float*)d_in[6];
    const float* ln1_b  = (const float*)d_in[7];
    const float* ln2_g  = (const float*)d_in[8];
    const float* ln2_b  = (const float*)d_in[9];
    const float* fc1_w  = (const float*)d_in[10];
    const float* fc1_b  = (const float*)d_in[11];
    const float* fc2_w  = (const float*)d_in[12];
    const float* fc2_b  = (const float*)d_in[13];
    float* out = (float*)d_out;

    float *s, *v, *pe;
    cudaGetSymbolAddress((void**)&s,  g_s);
    cudaGetSymbolAddress((void**)&v,  g_v);
    cudaGetSymbolAddress((void**)&pe, g_pe);
    __nv_bfloat16 *xh,*xl,*snh,*snl,*imh,*iml,*hh,*hl;
    __nv_bfloat16 *wh,*wl,*wvh,*wvl,*woh,*wol,*f1h,*f1l,*f2h,*f2l;
    cudaGetSymbolAddress((void**)&xh,  g_xh);  cudaGetSymbolAddress((void**)&xl,  g_xl);
    cudaGetSymbolAddress((void**)&snh, g_snh); cudaGetSymbolAddress((void**)&snl, g_snl);
    cudaGetSymbolAddress((void**)&imh, g_imh); cudaGetSymbolAddress((void**)&iml, g_iml);
    cudaGetSymbolAddress((void**)&hh,  g_hh);  cudaGetSymbolAddress((void**)&hl,  g_hl);
    cudaGetSymbolAddress((void**)&wh,  g_wh);  cudaGetSymbolAddress((void**)&wl,  g_wl);
    cudaGetSymbolAddress((void**)&wvh, g_wvh); cudaGetSymbolAddress((void**)&wvl, g_wvl);
    cudaGetSymbolAddress((void**)&woh, g_woh); cudaGetSymbolAddress((void**)&wol, g_wol);
    cudaGetSymbolAddress((void**)&f1h, g_f1h); cudaGetSymbolAddress((void**)&f1l, g_f1l);
    cudaGetSymbolAddress((void**)&f2h, g_f2h); cudaGetSymbolAddress((void**)&f2l, g_f2l);

    cudaFuncSetAttribute(hmma_gemm<0>, cudaFuncAttributeMaxDynamicSharedMemorySize, SMEMB);
    cudaFuncSetAttribute(hmma_gemm<1>, cudaFuncAttributeMaxDynamicSharedMemorySize, SMEMB);
    cudaFuncSetAttribute(hmma_gemm<2>, cudaFuncAttributeMaxDynamicSharedMemorySize, SMEMB);
    cudaFuncSetAttribute(hmma_gemm<3>, cudaFuncAttributeMaxDynamicSharedMemorySize, SMEMB);
    cudaFuncSetAttribute(hmma_gemm<4>, cudaFuncAttributeMaxDynamicSharedMemorySize, SMEMB);

    dim3 g768(MM / 64, ROWS / 128);    // (12, 32) = 384 CTAs
    dim3 g3072(HID / 64, ROWS / 128);  // (48, 32) = 1536 CTAs

    // launches 1-3: fused preps (launch #6 below = Wv GEMM for ncu -s 5)
    prep_a<<<1024, 256>>>(x, xh, xl, weight, wh, wl, pe);
    prep_pair<<<1024, 256>>>(Wv, wvh, wvl, Wo, woh, wol, TK * MM * MM);
    prep_pair<<<1024, 256>>>(fc1_w, f1h, f1l, fc2_w, f2h, f2l, HID * MM);

    // launch 4: prelude s = x @ weight^T + PE
    hmma_gemm<1><<<g768, 256, SMEMB>>>(xh, xl, wh, wl, nullptr, pe,
                                       s, nullptr, nullptr, MM, MM);

    for (int a = 0; a < TK; a++) {
        size_t off = (size_t)a * MM * MM;
        // sn = LN1(s)
        ln_split_kernel<false><<<ROWS, 256>>>(s, ln1_g, ln1_b, snh, snl);
        // v = sn @ Wv[a]^T   <-- launch #6 on a=0 (ncu profiles this)
        hmma_gemm<0><<<g768, 256, SMEMB>>>(snh, snl, wvh + off, wvl + off,
                                           nullptr, nullptr, v, nullptr, nullptr, MM, MM);
        // imv = exclusive cumsum over tokens
        scan_split_kernel<<<(NB * MM) / 256, 256>>>(v, imh, iml);
        // s = imv @ Wo[a]^T + s
        hmma_gemm<2><<<g768, 256, SMEMB>>>(imh, iml, woh + off, wol + off,
                                           nullptr, s, s, nullptr, nullptr, MM, MM);
        // t = LN2(s) + s
        ln_split_kernel<true><<<ROWS, 256>>>(s, ln2_g, ln2_b, snh, snl);
        // h = GELU(t @ fc1^T + b1)
        hmma_gemm<3><<<g3072, 256, SMEMB>>>(snh, snl, f1h, f1l, fc1_b, nullptr,
                                            nullptr, hh, hl, HID, MM);
        // s = h @ fc2^T + b2 (last stage -> d_out)
        float* dst = (a == TK - 1) ? out : s;
        hmma_gemm<4><<<g768, 256, SMEMB>>>(hh, hl, f2h, f2l, fc2_b, nullptr,
                                           dst, nullptr, nullptr, MM, HID);
    }
}